// round 2
// baseline (speedup 1.0000x reference)
#include <cuda_runtime.h>
#include <cstdint>
#include <math_constants.h>

// Problem constants
#define Bb 2
#define Ll 256
#define Ee 512
#define Hh 8
#define Dd 64
#define QSCALE 0.125f   // D^-0.5

// ---------------- device scratch (no allocations allowed) ----------------
__device__ float g_q[Bb*Ll*Ee];
__device__ float g_k[Bb*Ll*Ee];
__device__ float g_v[Bb*Ll*Ee];
__device__ float g_logits[(size_t)Bb*Hh*Ll*Ll];
__device__ float g_w[(size_t)Bb*Hh*Ll*Ll];
__device__ float g_o1[Bb*Ll*Ee];

// ---------------------------------------------------------------------------
// Generic small GEMM: Y[m,n] = (sum_k X[m,k]*W[n,k] + bias[n]) * scale
// M,N multiples of 64; K multiple of 16. 256 threads, 64x64 tile, 4x4 micro.
// ---------------------------------------------------------------------------
__global__ __launch_bounds__(256)
void gemm_bias_kernel(const float* __restrict__ X, const float* __restrict__ W,
                      const float* __restrict__ bias, float* __restrict__ Y,
                      int Mdim, int Ndim, int Kdim, float scale)
{
    __shared__ float Xs[16][64];
    __shared__ float Ws[16][64];
    int tid = threadIdx.x;
    int m0 = blockIdx.y * 64, n0 = blockIdx.x * 64;
    int ty = tid >> 4, tx = tid & 15;
    int r  = tid >> 2, c4 = tid & 3;

    float acc[4][4];
#pragma unroll
    for (int a = 0; a < 4; a++)
#pragma unroll
        for (int b = 0; b < 4; b++) acc[a][b] = 0.f;

    for (int kc = 0; kc < Kdim; kc += 16) {
        float4 xv = *(const float4*)(X + (size_t)(m0 + r) * Kdim + kc + c4 * 4);
        float4 wv = *(const float4*)(W + (size_t)(n0 + r) * Kdim + kc + c4 * 4);
        __syncthreads();
        Xs[c4*4+0][r] = xv.x; Xs[c4*4+1][r] = xv.y;
        Xs[c4*4+2][r] = xv.z; Xs[c4*4+3][r] = xv.w;
        Ws[c4*4+0][r] = wv.x; Ws[c4*4+1][r] = wv.y;
        Ws[c4*4+2][r] = wv.z; Ws[c4*4+3][r] = wv.w;
        __syncthreads();
#pragma unroll
        for (int c = 0; c < 16; c++) {
            float4 a = *(const float4*)&Xs[c][ty*4];
            float4 b = *(const float4*)&Ws[c][tx*4];
            acc[0][0] += a.x*b.x; acc[0][1] += a.x*b.y; acc[0][2] += a.x*b.z; acc[0][3] += a.x*b.w;
            acc[1][0] += a.y*b.x; acc[1][1] += a.y*b.y; acc[1][2] += a.y*b.z; acc[1][3] += a.y*b.w;
            acc[2][0] += a.z*b.x; acc[2][1] += a.z*b.y; acc[2][2] += a.z*b.z; acc[2][3] += a.z*b.w;
            acc[3][0] += a.w*b.x; acc[3][1] += a.w*b.y; acc[3][2] += a.w*b.z; acc[3][3] += a.w*b.w;
        }
    }
#pragma unroll
    for (int rr = 0; rr < 4; rr++) {
        int m = m0 + ty*4 + rr;
#pragma unroll
        for (int cc = 0; cc < 4; cc++) {
            int n = n0 + tx*4 + cc;
            Y[(size_t)m * Ndim + n] = (acc[rr][cc] + bias[n]) * scale;
        }
    }
}

// ---------------------------------------------------------------------------
// Fused relation projection + attention logits.
// CTA = (i_tile, j, b). Computes for 64 i-rows x 8 heads:
//   attn[b,i,j,h] = sum_d (q[b,i,h,d] + rq[b,j,i,h,d]) * (k[b,j,h,d] + rk[b,j,i,h,d])
// where [rq|rk](b,j,i) = Wr @ relation[b,j,i,:].
// ---------------------------------------------------------------------------
#define RA_OFF_CT (512*64)
#define RA_OFF_BS (RA_OFF_CT + 64*128)
#define RA_OFF_KS (RA_OFF_BS + 16*128)
#define RA_OFF_AT (RA_OFF_KS + 512)
#define RA_SMEM_BYTES ((RA_OFF_AT + 512) * 4)

__global__ __launch_bounds__(256, 1)
void rel_attn_kernel(const float* __restrict__ relation, const float* __restrict__ Wr)
{
    extern __shared__ float sm[];
    float* As     = sm;
    float* Ct     = sm + RA_OFF_CT;
    float* Bs     = sm + RA_OFF_BS;
    float* ks     = sm + RA_OFF_KS;
    float* attn_s = sm + RA_OFF_AT;

    int tid = threadIdx.x;
    int it = blockIdx.x, j = blockIdx.y, b = blockIdx.z;
    int i0 = it * 64;

    // Load A tile transposed: As[c][i] = relation[b, j, i0+i, c]
    const float* Rp = relation + (((size_t)b * Ll + j) * Ll + i0) * Ee;
    for (int idx = tid; idx < 64 * 128; idx += 256) {
        int i = idx & 63;
        int c4 = idx >> 6;
        float4 rv = *(const float4*)(Rp + (size_t)i * Ee + c4 * 4);
        As[(c4*4+0)*64 + i] = rv.x;
        As[(c4*4+1)*64 + i] = rv.y;
        As[(c4*4+2)*64 + i] = rv.z;
        As[(c4*4+3)*64 + i] = rv.w;
    }
    // Load k row for this (b, j)
    const float* Kp = g_k + ((size_t)b * Ll + j) * Ee;
    ks[tid]       = Kp[tid];
    ks[tid + 256] = Kp[tid + 256];
    __syncthreads();

    int ty = tid >> 4, tx = tid & 15;       // micro-tile 4 rows x 8 cols
    int o0 = tid >> 2, c40 = tid & 3;       // B-load mapping: o0 in [0,64)

    for (int h = 0; h < Hh; h++) {
        float acc[4][8];
#pragma unroll
        for (int a = 0; a < 4; a++)
#pragma unroll
            for (int n = 0; n < 8; n++) acc[a][n] = 0.f;

        const float* Wq_ptr = Wr + (size_t)(h*64 + o0) * Ee + c40 * 4;         // rq rows
        const float* Wk_ptr = Wr + (size_t)(512 + h*64 + o0) * Ee + c40 * 4;   // rk rows
        float4 w0 = *(const float4*)(Wq_ptr);   // prefetch chunk kc=0
        float4 w1 = *(const float4*)(Wk_ptr);

        for (int kc = 0; kc < Ee; kc += 16) {
            __syncthreads();   // Bs free from previous chunk's compute
            Bs[(c40*4+0)*128 + o0] = w0.x;
            Bs[(c40*4+1)*128 + o0] = w0.y;
            Bs[(c40*4+2)*128 + o0] = w0.z;
            Bs[(c40*4+3)*128 + o0] = w0.w;
            Bs[(c40*4+0)*128 + 64 + o0] = w1.x;
            Bs[(c40*4+1)*128 + 64 + o0] = w1.y;
            Bs[(c40*4+2)*128 + 64 + o0] = w1.z;
            Bs[(c40*4+3)*128 + 64 + o0] = w1.w;
            __syncthreads();
            if (kc + 16 < Ee) {   // register-staged prefetch of next chunk
                w0 = *(const float4*)(Wq_ptr + kc + 16);
                w1 = *(const float4*)(Wk_ptr + kc + 16);
            }
#pragma unroll
            for (int cc = 0; cc < 16; cc++) {
                const float* Arow = As + (kc + cc) * 64;
                float4 a   = *(const float4*)(Arow + ty * 4);
                float4 b0v = *(const float4*)(Bs + cc * 128 + tx * 8);
                float4 b1v = *(const float4*)(Bs + cc * 128 + tx * 8 + 4);
                acc[0][0]+=a.x*b0v.x; acc[0][1]+=a.x*b0v.y; acc[0][2]+=a.x*b0v.z; acc[0][3]+=a.x*b0v.w;
                acc[0][4]+=a.x*b1v.x; acc[0][5]+=a.x*b1v.y; acc[0][6]+=a.x*b1v.z; acc[0][7]+=a.x*b1v.w;
                acc[1][0]+=a.y*b0v.x; acc[1][1]+=a.y*b0v.y; acc[1][2]+=a.y*b0v.z; acc[1][3]+=a.y*b0v.w;
                acc[1][4]+=a.y*b1v.x; acc[1][5]+=a.y*b1v.y; acc[1][6]+=a.y*b1v.z; acc[1][7]+=a.y*b1v.w;
                acc[2][0]+=a.z*b0v.x; acc[2][1]+=a.z*b0v.y; acc[2][2]+=a.z*b0v.z; acc[2][3]+=a.z*b0v.w;
                acc[2][4]+=a.z*b1v.x; acc[2][5]+=a.z*b1v.y; acc[2][6]+=a.z*b1v.z; acc[2][7]+=a.z*b1v.w;
                acc[3][0]+=a.w*b0v.x; acc[3][1]+=a.w*b0v.y; acc[3][2]+=a.w*b0v.z; acc[3][3]+=a.w*b0v.w;
                acc[3][4]+=a.w*b1v.x; acc[3][5]+=a.w*b1v.y; acc[3][6]+=a.w*b1v.z; acc[3][7]+=a.w*b1v.w;
            }
        }
        // Stash tile: Ct[i][0:64]=rq_head, Ct[i][64:128]=rk_head
#pragma unroll
        for (int rr = 0; rr < 4; rr++)
#pragma unroll
            for (int nn = 0; nn < 8; nn++)
                Ct[(ty*4 + rr) * 128 + tx*8 + nn] = acc[rr][nn];
        __syncthreads();

        // Epilogue: 4 threads per i-row, 16 d's each, shfl-reduce
        {
            int i = tid >> 2, t = tid & 3;
            const float* qrow = g_q + (((size_t)b * Ll + i0 + i) * Ee + h * 64 + t * 16);
            const float* crow = Ct + i * 128 + t * 16;
            const float* krow = ks + h * 64 + t * 16;
            float s = 0.f;
#pragma unroll
            for (int dd = 0; dd < 16; dd++) {
                s += (qrow[dd] + crow[dd]) * (krow[dd] + crow[64 + dd]);
            }
            s += __shfl_down_sync(0xffffffffu, s, 1);
            s += __shfl_down_sync(0xffffffffu, s, 2);
            if (t == 0) attn_s[i * 8 + h] = s;
        }
        __syncthreads();
    }

    // Write logits in [b, h, i, j] layout (j innermost for softmax)
    // 512 entries, 256 threads -> strided loop (Round-1 bug was `if (tid<512)`)
    for (int idx = tid; idx < 64 * Hh; idx += 256) {
        int i = idx >> 3, hh = idx & 7;
        g_logits[(((size_t)b * Hh + hh) * Ll + i0 + i) * Ll + j] = attn_s[idx];
    }
}

// ---------------------------------------------------------------------------
// Masked softmax over j. One block per (b,h,i) row of 256 logits.
// ---------------------------------------------------------------------------
__global__ __launch_bounds__(256)
void softmax_kernel(const int* __restrict__ adj, float* __restrict__ out_attn)
{
    int i = blockIdx.x, h = blockIdx.y, b = blockIdx.z;
    int tid = threadIdx.x;
    __shared__ float red1[8];
    __shared__ float red2[8];

    size_t lbase = (((size_t)b * Hh + h) * Ll + i) * Ll;
    float x = g_logits[lbase + tid];
    bool masked = (adj[((size_t)b * Ll + i) * Ll + tid] == 1);
    float xv = masked ? -CUDART_INF_F : x;

    float mx = xv;
#pragma unroll
    for (int o = 16; o > 0; o >>= 1) mx = fmaxf(mx, __shfl_xor_sync(0xffffffffu, mx, o));
    if ((tid & 31) == 0) red1[tid >> 5] = mx;
    __syncthreads();
    mx = red1[0];
#pragma unroll
    for (int w = 1; w < 8; w++) mx = fmaxf(mx, red1[w]);

    float e = masked ? 0.f : expf(xv - mx);
    float s = e;
#pragma unroll
    for (int o = 16; o > 0; o >>= 1) s += __shfl_xor_sync(0xffffffffu, s, o);
    if ((tid & 31) == 0) red2[tid >> 5] = s;
    __syncthreads();
    s = red2[0];
#pragma unroll
    for (int w = 1; w < 8; w++) s += red2[w];

    float wgt = e / s;
    g_w[lbase + tid] = wgt;
    out_attn[(((size_t)b * Ll + i) * Ll + tid) * Hh + h] = wgt;
}

// ---------------------------------------------------------------------------
// PV: o1[b,i,h,d] = sum_j w[b,h,i,j] * v[b,j,h,d]
// ---------------------------------------------------------------------------
#define PV_SMEM_BYTES ((64*256 + 256*64) * 4)

__global__ __launch_bounds__(256, 1)
void pv_kernel()
{
    extern __shared__ float sm[];
    float* Ws = sm;            // [64][256]
    float* Vs = sm + 64 * 256; // [256][64]
    int it = blockIdx.x, h = blockIdx.y, b = blockIdx.z;
    int i0 = it * 64;
    int tid = threadIdx.x;

    size_t wbase = (((size_t)b * Hh + h) * Ll + i0) * Ll;
    const float4* wsrc = (const float4*)(g_w + wbase);
    float4* wdst = (float4*)Ws;
    for (int idx = tid; idx < 64 * 256 / 4; idx += 256) wdst[idx] = wsrc[idx];

    float4* vdst = (float4*)Vs;
    for (int idx = tid; idx < 256 * 64 / 4; idx += 256) {
        int jrow = idx >> 4;
        int d4 = idx & 15;
        vdst[idx] = *(const float4*)(g_v + ((size_t)b * Ll + jrow) * Ee + h * 64 + d4 * 4);
    }
    __syncthreads();

    int i = tid >> 2, t = tid & 3;
    float acc[16];
#pragma unroll
    for (int dd = 0; dd < 16; dd++) acc[dd] = 0.f;

    const float* wrow = Ws + i * 256;
    for (int jj = 0; jj < 256; jj += 4) {
        float4 wv = *(const float4*)(wrow + jj);
#pragma unroll
        for (int u = 0; u < 4; u++) {
            float wsc = (u == 0) ? wv.x : (u == 1) ? wv.y : (u == 2) ? wv.z : wv.w;
            const float* vr = Vs + (jj + u) * 64 + t * 16;
#pragma unroll
            for (int dd = 0; dd < 16; dd++) acc[dd] += wsc * vr[dd];
        }
    }
    float* op = g_o1 + ((size_t)b * Ll + i0 + i) * Ee + h * 64 + t * 16;
#pragma unroll
    for (int dd = 0; dd < 16; dd++) op[dd] = acc[dd];
}

// ---------------------------------------------------------------------------
extern "C" void kernel_launch(void* const* d_in, const int* in_sizes, int n_in,
                              void* d_out, int out_size)
{
    (void)in_sizes; (void)n_in; (void)out_size;
    const float* queries  = (const float*)d_in[0];
    const float* keys     = (const float*)d_in[1];
    const float* values   = (const float*)d_in[2];
    const float* relation = (const float*)d_in[3];
    const int*   adj      = (const int*)d_in[4];
    const float* Wq = (const float*)d_in[5];
    const float* bq = (const float*)d_in[6];
    const float* Wk = (const float*)d_in[7];
    const float* bk = (const float*)d_in[8];
    const float* Wv = (const float*)d_in[9];
    const float* bv = (const float*)d_in[10];
    const float* Wr = (const float*)d_in[11];
    const float* Wo = (const float*)d_in[12];
    const float* bo = (const float*)d_in[13];

    float* out      = (float*)d_out;              // [B, L, E]
    float* out_attn = out + Bb * Ll * Ee;         // [B, L, L, H]

    float *qp, *kp, *vp, *o1p;
    cudaGetSymbolAddress((void**)&qp,  g_q);
    cudaGetSymbolAddress((void**)&kp,  g_k);
    cudaGetSymbolAddress((void**)&vp,  g_v);
    cudaGetSymbolAddress((void**)&o1p, g_o1);

    cudaFuncSetAttribute(rel_attn_kernel, cudaFuncAttributeMaxDynamicSharedMemorySize, RA_SMEM_BYTES);
    cudaFuncSetAttribute(pv_kernel, cudaFuncAttributeMaxDynamicSharedMemorySize, PV_SMEM_BYTES);

    dim3 gproj(Ee / 64, (Bb * Ll) / 64);
    gemm_bias_kernel<<<gproj, 256>>>(queries, Wq, bq, qp, Bb*Ll, Ee, Ee, QSCALE);
    gemm_bias_kernel<<<gproj, 256>>>(keys,    Wk, bk, kp, Bb*Ll, Ee, Ee, 1.0f);
    gemm_bias_kernel<<<gproj, 256>>>(values,  Wv, bv, vp, Bb*Ll, Ee, Ee, 1.0f);

    rel_attn_kernel<<<dim3(Ll / 64, Ll, Bb), 256, RA_SMEM_BYTES>>>(relation, Wr);

    softmax_kernel<<<dim3(Ll, Hh, Bb), 256>>>(adj, out_attn);

    pv_kernel<<<dim3(Ll / 64, Hh, Bb), 256, PV_SMEM_BYTES>>>();

    gemm_bias_kernel<<<gproj, 256>>>(o1p, Wo, bo, out, Bb*Ll, Ee, Ee, 1.0f);
}

// round 3
// speedup vs baseline: 1.0002x; 1.0002x over previous
#include <cuda_runtime.h>
#include <cstdint>
#include <math_constants.h>

// Problem constants
#define Bb 2
#define Ll 256
#define Ee 512
#define Hh 8
#define Dd 64
#define QSCALE 0.125f   // D^-0.5

// ---------------- device scratch (no allocations allowed) ----------------
__device__ float g_q[Bb*Ll*Ee];
__device__ float g_k[Bb*Ll*Ee];
__device__ float g_v[Bb*Ll*Ee];
__device__ float g_logits[(size_t)Bb*Hh*Ll*Ll];
__device__ float g_w[(size_t)Bb*Hh*Ll*Ll];
__device__ float g_o1[Bb*Ll*Ee];

// ---------------------------------------------------------------------------
// Generic small GEMM: Y[m,n] = (sum_k X[m,k]*W[n,k] + bias[n]) * scale
// M,N multiples of 64; K multiple of 16. 256 threads, 64x64 tile, 4x4 micro.
// ---------------------------------------------------------------------------
__global__ __launch_bounds__(256)
void gemm_bias_kernel(const float* __restrict__ X, const float* __restrict__ W,
                      const float* __restrict__ bias, float* __restrict__ Y,
                      int Mdim, int Ndim, int Kdim, float scale)
{
    __shared__ float Xs[16][64];
    __shared__ float Ws[16][64];
    int tid = threadIdx.x;
    int m0 = blockIdx.y * 64, n0 = blockIdx.x * 64;
    int ty = tid >> 4, tx = tid & 15;
    int r  = tid >> 2, c4 = tid & 3;

    float acc[4][4];
#pragma unroll
    for (int a = 0; a < 4; a++)
#pragma unroll
        for (int b = 0; b < 4; b++) acc[a][b] = 0.f;

    for (int kc = 0; kc < Kdim; kc += 16) {
        float4 xv = *(const float4*)(X + (size_t)(m0 + r) * Kdim + kc + c4 * 4);
        float4 wv = *(const float4*)(W + (size_t)(n0 + r) * Kdim + kc + c4 * 4);
        __syncthreads();
        Xs[c4*4+0][r] = xv.x; Xs[c4*4+1][r] = xv.y;
        Xs[c4*4+2][r] = xv.z; Xs[c4*4+3][r] = xv.w;
        Ws[c4*4+0][r] = wv.x; Ws[c4*4+1][r] = wv.y;
        Ws[c4*4+2][r] = wv.z; Ws[c4*4+3][r] = wv.w;
        __syncthreads();
#pragma unroll
        for (int c = 0; c < 16; c++) {
            float4 a = *(const float4*)&Xs[c][ty*4];
            float4 b = *(const float4*)&Ws[c][tx*4];
            acc[0][0] += a.x*b.x; acc[0][1] += a.x*b.y; acc[0][2] += a.x*b.z; acc[0][3] += a.x*b.w;
            acc[1][0] += a.y*b.x; acc[1][1] += a.y*b.y; acc[1][2] += a.y*b.z; acc[1][3] += a.y*b.w;
            acc[2][0] += a.z*b.x; acc[2][1] += a.z*b.y; acc[2][2] += a.z*b.z; acc[2][3] += a.z*b.w;
            acc[3][0] += a.w*b.x; acc[3][1] += a.w*b.y; acc[3][2] += a.w*b.z; acc[3][3] += a.w*b.w;
        }
    }
#pragma unroll
    for (int rr = 0; rr < 4; rr++) {
        int m = m0 + ty*4 + rr;
#pragma unroll
        for (int cc = 0; cc < 4; cc++) {
            int n = n0 + tx*4 + cc;
            Y[(size_t)m * Ndim + n] = (acc[rr][cc] + bias[n]) * scale;
        }
    }
}

// ---------------------------------------------------------------------------
// Fused relation projection + attention logits.
// CTA = (i_tile, j, b). Computes for 64 i-rows x 8 heads:
//   attn[b,i,j,h] = sum_d (q[b,i,h,d] + rq[b,j,i,h,d]) * (k[b,j,h,d] + rk[b,j,i,h,d])
// where [rq|rk](b,j,i) = Wr @ relation[b,j,i,:].
// ---------------------------------------------------------------------------
#define RA_OFF_CT (512*64)
#define RA_OFF_BS (RA_OFF_CT + 64*128)
#define RA_OFF_KS (RA_OFF_BS + 16*128)
#define RA_OFF_AT (RA_OFF_KS + 512)
#define RA_SMEM_BYTES ((RA_OFF_AT + 512) * 4)

__global__ __launch_bounds__(256, 1)
void rel_attn_kernel(const float* __restrict__ relation, const float* __restrict__ Wr)
{
    extern __shared__ float sm[];
    float* As     = sm;
    float* Ct     = sm + RA_OFF_CT;
    float* Bs     = sm + RA_OFF_BS;
    float* ks     = sm + RA_OFF_KS;
    float* attn_s = sm + RA_OFF_AT;

    int tid = threadIdx.x;
    int it = blockIdx.x, j = blockIdx.y, b = blockIdx.z;
    int i0 = it * 64;

    // Load A tile transposed: As[c][i] = relation[b, j, i0+i, c]
    const float* Rp = relation + (((size_t)b * Ll + j) * Ll + i0) * Ee;
    for (int idx = tid; idx < 64 * 128; idx += 256) {
        int i = idx & 63;
        int c4 = idx >> 6;
        float4 rv = *(const float4*)(Rp + (size_t)i * Ee + c4 * 4);
        As[(c4*4+0)*64 + i] = rv.x;
        As[(c4*4+1)*64 + i] = rv.y;
        As[(c4*4+2)*64 + i] = rv.z;
        As[(c4*4+3)*64 + i] = rv.w;
    }
    // Load k row for this (b, j)
    const float* Kp = g_k + ((size_t)b * Ll + j) * Ee;
    ks[tid]       = Kp[tid];
    ks[tid + 256] = Kp[tid + 256];
    __syncthreads();

    int ty = tid >> 4, tx = tid & 15;       // micro-tile 4 rows x 8 cols
    int o0 = tid >> 2, c40 = tid & 3;       // B-load mapping: o0 in [0,64)

    for (int h = 0; h < Hh; h++) {
        float acc[4][8];
#pragma unroll
        for (int a = 0; a < 4; a++)
#pragma unroll
            for (int n = 0; n < 8; n++) acc[a][n] = 0.f;

        const float* Wq_ptr = Wr + (size_t)(h*64 + o0) * Ee + c40 * 4;         // rq rows
        const float* Wk_ptr = Wr + (size_t)(512 + h*64 + o0) * Ee + c40 * 4;   // rk rows
        float4 w0 = *(const float4*)(Wq_ptr);   // prefetch chunk kc=0
        float4 w1 = *(const float4*)(Wk_ptr);

        for (int kc = 0; kc < Ee; kc += 16) {
            __syncthreads();   // Bs free from previous chunk's compute
            Bs[(c40*4+0)*128 + o0] = w0.x;
            Bs[(c40*4+1)*128 + o0] = w0.y;
            Bs[(c40*4+2)*128 + o0] = w0.z;
            Bs[(c40*4+3)*128 + o0] = w0.w;
            Bs[(c40*4+0)*128 + 64 + o0] = w1.x;
            Bs[(c40*4+1)*128 + 64 + o0] = w1.y;
            Bs[(c40*4+2)*128 + 64 + o0] = w1.z;
            Bs[(c40*4+3)*128 + 64 + o0] = w1.w;
            __syncthreads();
            if (kc + 16 < Ee) {   // register-staged prefetch of next chunk
                w0 = *(const float4*)(Wq_ptr + kc + 16);
                w1 = *(const float4*)(Wk_ptr + kc + 16);
            }
#pragma unroll
            for (int cc = 0; cc < 16; cc++) {
                const float* Arow = As + (kc + cc) * 64;
                float4 a   = *(const float4*)(Arow + ty * 4);
                float4 b0v = *(const float4*)(Bs + cc * 128 + tx * 8);
                float4 b1v = *(const float4*)(Bs + cc * 128 + tx * 8 + 4);
                acc[0][0]+=a.x*b0v.x; acc[0][1]+=a.x*b0v.y; acc[0][2]+=a.x*b0v.z; acc[0][3]+=a.x*b0v.w;
                acc[0][4]+=a.x*b1v.x; acc[0][5]+=a.x*b1v.y; acc[0][6]+=a.x*b1v.z; acc[0][7]+=a.x*b1v.w;
                acc[1][0]+=a.y*b0v.x; acc[1][1]+=a.y*b0v.y; acc[1][2]+=a.y*b0v.z; acc[1][3]+=a.y*b0v.w;
                acc[1][4]+=a.y*b1v.x; acc[1][5]+=a.y*b1v.y; acc[1][6]+=a.y*b1v.z; acc[1][7]+=a.y*b1v.w;
                acc[2][0]+=a.z*b0v.x; acc[2][1]+=a.z*b0v.y; acc[2][2]+=a.z*b0v.z; acc[2][3]+=a.z*b0v.w;
                acc[2][4]+=a.z*b1v.x; acc[2][5]+=a.z*b1v.y; acc[2][6]+=a.z*b1v.z; acc[2][7]+=a.z*b1v.w;
                acc[3][0]+=a.w*b0v.x; acc[3][1]+=a.w*b0v.y; acc[3][2]+=a.w*b0v.z; acc[3][3]+=a.w*b0v.w;
                acc[3][4]+=a.w*b1v.x; acc[3][5]+=a.w*b1v.y; acc[3][6]+=a.w*b1v.z; acc[3][7]+=a.w*b1v.w;
            }
        }
        // Stash tile: Ct[i][0:64]=rq_head, Ct[i][64:128]=rk_head
#pragma unroll
        for (int rr = 0; rr < 4; rr++)
#pragma unroll
            for (int nn = 0; nn < 8; nn++)
                Ct[(ty*4 + rr) * 128 + tx*8 + nn] = acc[rr][nn];
        __syncthreads();

        // Epilogue: 4 threads per i-row, 16 d's each, shfl-reduce
        {
            int i = tid >> 2, t = tid & 3;
            const float* qrow = g_q + (((size_t)b * Ll + i0 + i) * Ee + h * 64 + t * 16);
            const float* crow = Ct + i * 128 + t * 16;
            const float* krow = ks + h * 64 + t * 16;
            float s = 0.f;
#pragma unroll
            for (int dd = 0; dd < 16; dd++) {
                s += (qrow[dd] + crow[dd]) * (krow[dd] + crow[64 + dd]);
            }
            s += __shfl_down_sync(0xffffffffu, s, 1);
            s += __shfl_down_sync(0xffffffffu, s, 2);
            if (t == 0) attn_s[i * 8 + h] = s;
        }
        __syncthreads();
    }

    // Write logits in [b, h, i, j] layout (j innermost for softmax)
    // 512 entries, 256 threads -> strided loop (Round-1 bug was `if (tid<512)`)
    for (int idx = tid; idx < 64 * Hh; idx += 256) {
        int i = idx >> 3, hh = idx & 7;
        g_logits[(((size_t)b * Hh + hh) * Ll + i0 + i) * Ll + j] = attn_s[idx];
    }
}

// ---------------------------------------------------------------------------
// Masked softmax over j. One block per (b,h,i) row of 256 logits.
// ---------------------------------------------------------------------------
__global__ __launch_bounds__(256)
void softmax_kernel(const int* __restrict__ adj, float* __restrict__ out_attn)
{
    int i = blockIdx.x, h = blockIdx.y, b = blockIdx.z;
    int tid = threadIdx.x;
    __shared__ float red1[8];
    __shared__ float red2[8];

    size_t lbase = (((size_t)b * Hh + h) * Ll + i) * Ll;
    float x = g_logits[lbase + tid];
    bool masked = (adj[((size_t)b * Ll + i) * Ll + tid] == 1);
    float xv = masked ? -CUDART_INF_F : x;

    float mx = xv;
#pragma unroll
    for (int o = 16; o > 0; o >>= 1) mx = fmaxf(mx, __shfl_xor_sync(0xffffffffu, mx, o));
    if ((tid & 31) == 0) red1[tid >> 5] = mx;
    __syncthreads();
    mx = red1[0];
#pragma unroll
    for (int w = 1; w < 8; w++) mx = fmaxf(mx, red1[w]);

    float e = masked ? 0.f : expf(xv - mx);
    float s = e;
#pragma unroll
    for (int o = 16; o > 0; o >>= 1) s += __shfl_xor_sync(0xffffffffu, s, o);
    if ((tid & 31) == 0) red2[tid >> 5] = s;
    __syncthreads();
    s = red2[0];
#pragma unroll
    for (int w = 1; w < 8; w++) s += red2[w];

    float wgt = e / s;
    g_w[lbase + tid] = wgt;
    out_attn[(((size_t)b * Ll + i) * Ll + tid) * Hh + h] = wgt;
}

// ---------------------------------------------------------------------------
// PV: o1[b,i,h,d] = sum_j w[b,h,i,j] * v[b,j,h,d]
// ---------------------------------------------------------------------------
#define PV_SMEM_BYTES ((64*256 + 256*64) * 4)

__global__ __launch_bounds__(256, 1)
void pv_kernel()
{
    extern __shared__ float sm[];
    float* Ws = sm;            // [64][256]
    float* Vs = sm + 64 * 256; // [256][64]
    int it = blockIdx.x, h = blockIdx.y, b = blockIdx.z;
    int i0 = it * 64;
    int tid = threadIdx.x;

    size_t wbase = (((size_t)b * Hh + h) * Ll + i0) * Ll;
    const float4* wsrc = (const float4*)(g_w + wbase);
    float4* wdst = (float4*)Ws;
    for (int idx = tid; idx < 64 * 256 / 4; idx += 256) wdst[idx] = wsrc[idx];

    float4* vdst = (float4*)Vs;
    for (int idx = tid; idx < 256 * 64 / 4; idx += 256) {
        int jrow = idx >> 4;
        int d4 = idx & 15;
        vdst[idx] = *(const float4*)(g_v + ((size_t)b * Ll + jrow) * Ee + h * 64 + d4 * 4);
    }
    __syncthreads();

    int i = tid >> 2, t = tid & 3;
    float acc[16];
#pragma unroll
    for (int dd = 0; dd < 16; dd++) acc[dd] = 0.f;

    const float* wrow = Ws + i * 256;
    for (int jj = 0; jj < 256; jj += 4) {
        float4 wv = *(const float4*)(wrow + jj);
#pragma unroll
        for (int u = 0; u < 4; u++) {
            float wsc = (u == 0) ? wv.x : (u == 1) ? wv.y : (u == 2) ? wv.z : wv.w;
            const float* vr = Vs + (jj + u) * 64 + t * 16;
#pragma unroll
            for (int dd = 0; dd < 16; dd++) acc[dd] += wsc * vr[dd];
        }
    }
    float* op = g_o1 + ((size_t)b * Ll + i0 + i) * Ee + h * 64 + t * 16;
#pragma unroll
    for (int dd = 0; dd < 16; dd++) op[dd] = acc[dd];
}

// ---------------------------------------------------------------------------
extern "C" void kernel_launch(void* const* d_in, const int* in_sizes, int n_in,
                              void* d_out, int out_size)
{
    (void)in_sizes; (void)n_in; (void)out_size;
    const float* queries  = (const float*)d_in[0];
    const float* keys     = (const float*)d_in[1];
    const float* values   = (const float*)d_in[2];
    const float* relation = (const float*)d_in[3];
    const int*   adj      = (const int*)d_in[4];
    const float* Wq = (const float*)d_in[5];
    const float* bq = (const float*)d_in[6];
    const float* Wk = (const float*)d_in[7];
    const float* bk = (const float*)d_in[8];
    const float* Wv = (const float*)d_in[9];
    const float* bv = (const float*)d_in[10];
    const float* Wr = (const float*)d_in[11];
    const float* Wo = (const float*)d_in[12];
    const float* bo = (const float*)d_in[13];

    float* out      = (float*)d_out;              // [B, L, E]
    float* out_attn = out + Bb * Ll * Ee;         // [B, L, L, H]

    float *qp, *kp, *vp, *o1p;
    cudaGetSymbolAddress((void**)&qp,  g_q);
    cudaGetSymbolAddress((void**)&kp,  g_k);
    cudaGetSymbolAddress((void**)&vp,  g_v);
    cudaGetSymbolAddress((void**)&o1p, g_o1);

    cudaFuncSetAttribute(rel_attn_kernel, cudaFuncAttributeMaxDynamicSharedMemorySize, RA_SMEM_BYTES);
    cudaFuncSetAttribute(pv_kernel, cudaFuncAttributeMaxDynamicSharedMemorySize, PV_SMEM_BYTES);

    dim3 gproj(Ee / 64, (Bb * Ll) / 64);
    gemm_bias_kernel<<<gproj, 256>>>(queries, Wq, bq, qp, Bb*Ll, Ee, Ee, QSCALE);
    gemm_bias_kernel<<<gproj, 256>>>(keys,    Wk, bk, kp, Bb*Ll, Ee, Ee, 1.0f);
    gemm_bias_kernel<<<gproj, 256>>>(values,  Wv, bv, vp, Bb*Ll, Ee, Ee, 1.0f);

    rel_attn_kernel<<<dim3(Ll / 64, Ll, Bb), 256, RA_SMEM_BYTES>>>(relation, Wr);

    softmax_kernel<<<dim3(Ll, Hh, Bb), 256>>>(adj, out_attn);

    pv_kernel<<<dim3(Ll / 64, Hh, Bb), 256, PV_SMEM_BYTES>>>();

    gemm_bias_kernel<<<gproj, 256>>>(o1p, Wo, bo, out, Bb*Ll, Ee, Ee, 1.0f);
}

// round 5
// speedup vs baseline: 3.4568x; 3.4562x over previous
#include <cuda_runtime.h>
#include <cuda_bf16.h>
#include <cstdint>
#include <math_constants.h>

#define Bb 2
#define Ll 256
#define Ee 512
#define Hh 8
#define QSCALE 0.125f

// ---------------- device scratch ----------------
__device__ float g_q[Bb*Ll*Ee];
__device__ float g_k[Bb*Ll*Ee];
__device__ float g_v[Bb*Ll*Ee];
__device__ float g_logits[(size_t)Bb*Hh*Ll*Ll];
__device__ float g_w[(size_t)Bb*Hh*Ll*Ll];
__device__ float g_o1[Bb*Ll*Ee];
__device__ __nv_bfloat16 g_rel_hi[(size_t)Bb*Ll*Ll*Ee];
__device__ __nv_bfloat16 g_rel_lo[(size_t)Bb*Ll*Ll*Ee];
__device__ __nv_bfloat16 g_w_hi[1024*512];  // [h*128+p][k]; p<64: Wrq rows, p>=64: Wrk rows
__device__ __nv_bfloat16 g_w_lo[1024*512];

// ==================== PTX helpers (sm_103 baseline only) ====================
__device__ __forceinline__ uint32_t smem_u32(const void* p) {
    uint32_t a;
    asm("{ .reg .u64 t; cvta.to.shared.u64 t, %1; cvt.u32.u64 %0, t; }" : "=r"(a) : "l"(p));
    return a;
}
#define SMEM_SWZ(o) ((o) ^ (((o) >> 3) & 0x70))
#define CP_ASYNC16(dst, src) \
    asm volatile("cp.async.cg.shared.global [%0], [%1], 16;" :: "r"(dst), "l"(src))
#define CP_COMMIT() asm volatile("cp.async.commit_group;" ::: "memory")
#define CP_WAIT1() asm volatile("cp.async.wait_group 1;" ::: "memory")
#define CP_WAIT0() asm volatile("cp.async.wait_group 0;" ::: "memory")

__device__ __forceinline__ void ldmx4(uint32_t& r0, uint32_t& r1, uint32_t& r2, uint32_t& r3, uint32_t addr) {
    asm volatile("ldmatrix.sync.aligned.m8n8.x4.shared.b16 {%0,%1,%2,%3}, [%4];"
        : "=r"(r0), "=r"(r1), "=r"(r2), "=r"(r3) : "r"(addr));
}
__device__ __forceinline__ void mma_bf16(float* c, const uint32_t* a, uint32_t b0, uint32_t b1) {
    asm volatile("mma.sync.aligned.m16n8k16.row.col.f32.bf16.bf16.f32 "
        "{%0,%1,%2,%3}, {%4,%5,%6,%7}, {%8,%9}, {%0,%1,%2,%3};"
        : "+f"(c[0]), "+f"(c[1]), "+f"(c[2]), "+f"(c[3])
        : "r"(a[0]), "r"(a[1]), "r"(a[2]), "r"(a[3]), "r"(b0), "r"(b1));
}

// ==================== split kernels ====================
__device__ __forceinline__ void split4(float4 v, __nv_bfloat16* hp, __nv_bfloat16* lp) {
    __nv_bfloat16 h0=__float2bfloat16_rn(v.x), h1=__float2bfloat16_rn(v.y);
    __nv_bfloat16 h2=__float2bfloat16_rn(v.z), h3=__float2bfloat16_rn(v.w);
    ((__nv_bfloat162*)hp)[0] = __nv_bfloat162{h0,h1};
    ((__nv_bfloat162*)hp)[1] = __nv_bfloat162{h2,h3};
    ((__nv_bfloat162*)lp)[0] = __nv_bfloat162{__float2bfloat16_rn(v.x-__bfloat162float(h0)),
                                              __float2bfloat16_rn(v.y-__bfloat162float(h1))};
    ((__nv_bfloat162*)lp)[1] = __nv_bfloat162{__float2bfloat16_rn(v.z-__bfloat162float(h2)),
                                              __float2bfloat16_rn(v.w-__bfloat162float(h3))};
}
__global__ void split_rel_kernel(const float4* __restrict__ x) {
    size_t i = (size_t)blockIdx.x * 256 + threadIdx.x;
    split4(x[i], g_rel_hi + i*4, g_rel_lo + i*4);
}
__global__ void split_w_kernel(const float* __restrict__ Wr) {
    int r = blockIdx.x;                 // 0..1023
    int h = r >> 7, p = r & 127;
    int in_row = (p < 64) ? (h*64 + p) : (512 + h*64 + (p - 64));
    int t = threadIdx.x;                // 128 threads
    float4 v = ((const float4*)(Wr + (size_t)in_row * 512))[t];
    split4(v, g_w_hi + (size_t)r*512 + t*4, g_w_lo + (size_t)r*512 + t*4);
}

// ==================== mma.sync relation attention ====================
// CTA per (i_tile 128, j, b). Heads looped inside; per head 24 chunks of
// K=64: splits [Ah*Bh(8) | Ah*Bl(8) | Al*Bh(8)]. 3-stage cp.async pipeline.
// Warps: 4m x 2n; warp tile 32(M) x 64(N, matched rq/rk halves).
#define NSTG 3
#define STG_BYTES 32768         // A 16KB + B 16KB
#define MMA_SMEM (NSTG*STG_BYTES + 1024)   // + parr 256 floats

__global__ void __launch_bounds__(256, 1) rel_attn_mma_kernel()
{
    extern __shared__ char smem[];
    float* parr = (float*)(smem + NSTG * STG_BYTES);
    const uint32_t sb = smem_u32(smem);
    const int tid = threadIdx.x, lane = tid & 31, w = tid >> 5;
    const int wm = w & 3, wn = w >> 2;
    const int it = blockIdx.x, j = blockIdx.y, b = blockIdx.z;
    const int i0 = it * 128;
    const size_t arow0 = ((size_t)(b * Ll + j)) * Ll + i0;

    float c[2][8][4];
#pragma unroll
    for (int mt = 0; mt < 2; mt++)
#pragma unroll
        for (int g = 0; g < 8; g++)
#pragma unroll
            for (int e = 0; e < 4; e++) c[mt][g][e] = 0.f;

    auto issue = [&](int gc) {
        const int h = gc / 24, cc = gc % 24;
        const int split = cc >> 3;
        const int kc = (cc & 7) * 64;
        const __nv_bfloat16* Aarr = (split == 2) ? g_rel_lo : g_rel_hi;
        const __nv_bfloat16* Bptr = ((split == 1) ? g_w_lo : g_w_hi) + (size_t)h * 128 * 512;
        const uint32_t stA = sb + (gc % NSTG) * STG_BYTES;
        const uint32_t stB = stA + 16384;
#pragma unroll
        for (int r4 = 0; r4 < 4; r4++) {
            int idx = tid + r4 * 256;       // 1024 16B units each
            int row = idx >> 3, u = idx & 7;
            CP_ASYNC16(stA + SMEM_SWZ(row * 128 + u * 16), Aarr + (arow0 + row) * 512 + kc + u * 8);
            CP_ASYNC16(stB + SMEM_SWZ(row * 128 + u * 16), Bptr + (size_t)row * 512 + kc + u * 8);
        }
        CP_COMMIT();
    };

    issue(0); issue(1);

    for (int gc = 0; gc < 192; gc++) {
        if (gc + 2 < 192) { CP_WAIT1(); } else { CP_WAIT0(); }
        __syncthreads();
        if (gc + 2 < 192) issue(gc + 2);

        const uint32_t stA = sb + (gc % NSTG) * STG_BYTES;
        const uint32_t stB = stA + 16384;
        const int r8 = lane & 7, sel = lane >> 3;
#pragma unroll
        for (int ks = 0; ks < 4; ks++) {
            const int k0 = ks * 16;
            uint32_t a[2][4];
#pragma unroll
            for (int mt = 0; mt < 2; mt++) {
                int row = wm * 32 + mt * 16 + r8 + (sel & 1) * 8;
                int c16 = (k0 >> 3) + (sel >> 1);
                ldmx4(a[mt][0], a[mt][1], a[mt][2], a[mt][3], stA + SMEM_SWZ(row * 128 + c16 * 16));
            }
            uint32_t bq[4][2], bk[4][2];
#pragma unroll
            for (int gp = 0; gp < 2; gp++) {
                int c16 = (k0 >> 3) + (sel & 1);
                {
                    int row = wn * 32 + gp * 16 + r8 + (sel >> 1) * 8;
                    ldmx4(bq[gp*2][0], bq[gp*2][1], bq[gp*2+1][0], bq[gp*2+1][1],
                          stB + SMEM_SWZ(row * 128 + c16 * 16));
                }
                {
                    int row = 64 + wn * 32 + gp * 16 + r8 + (sel >> 1) * 8;
                    ldmx4(bk[gp*2][0], bk[gp*2][1], bk[gp*2+1][0], bk[gp*2+1][1],
                          stB + SMEM_SWZ(row * 128 + c16 * 16));
                }
            }
#pragma unroll
            for (int mt = 0; mt < 2; mt++)
#pragma unroll
                for (int g = 0; g < 4; g++) {
                    mma_bf16(c[mt][g],     a[mt], bq[g][0], bq[g][1]);
                    mma_bf16(c[mt][4+g],   a[mt], bk[g][0], bk[g][1]);
                }
        }

        if ((gc % 24) == 23) {
            // -------- epilogue for head h --------
            const int h = gc / 24;
            const float* qb = g_q + ((size_t)(b * Ll) + i0) * Ee + h * 64;
            const float* kb = g_k + ((size_t)(b * Ll + j)) * Ee + h * 64;
#pragma unroll
            for (int mt = 0; mt < 2; mt++)
#pragma unroll
                for (int rh = 0; rh < 2; rh++) {
                    const int R = wm * 32 + mt * 16 + (lane >> 2) + rh * 8;
                    float acc = 0.f;
#pragma unroll
                    for (int g = 0; g < 4; g++) {
                        const int d0 = wn * 32 + g * 8 + 2 * (lane & 3);
                        acc += (qb[(size_t)R * Ee + d0]     + c[mt][g][rh*2+0]) *
                               (kb[d0]     + c[mt][4+g][rh*2+0]);
                        acc += (qb[(size_t)R * Ee + d0 + 1] + c[mt][g][rh*2+1]) *
                               (kb[d0 + 1] + c[mt][4+g][rh*2+1]);
                    }
                    acc += __shfl_xor_sync(0xffffffffu, acc, 1);
                    acc += __shfl_xor_sync(0xffffffffu, acc, 2);
                    if ((lane & 3) == 0) parr[wn * 128 + R] = acc;
                }
            __syncthreads();
            if (tid < 128) {
                float lg = parr[tid] + parr[128 + tid];
                g_logits[((size_t)(b * Hh + h) * Ll + i0 + tid) * Ll + j] = lg;
            }
            // reset accumulators for next head
#pragma unroll
            for (int mt = 0; mt < 2; mt++)
#pragma unroll
                for (int g = 0; g < 8; g++)
#pragma unroll
                    for (int e = 0; e < 4; e++) c[mt][g][e] = 0.f;
        }
    }
}

// ==================== small GEMM / softmax / PV ====================
__global__ __launch_bounds__(256)
void gemm_bias_kernel(const float* __restrict__ X, const float* __restrict__ W,
                      const float* __restrict__ bias, float* __restrict__ Y,
                      int Mdim, int Ndim, int Kdim, float scale)
{
    __shared__ float Xs[16][64];
    __shared__ float Ws[16][64];
    int tid = threadIdx.x;
    int m0 = blockIdx.y * 64, n0 = blockIdx.x * 64;
    int ty = tid >> 4, tx = tid & 15;
    int r = tid >> 2, c4 = tid & 3;
    float acc[4][4];
#pragma unroll
    for (int a = 0; a < 4; a++)
#pragma unroll
        for (int bq = 0; bq < 4; bq++) acc[a][bq] = 0.f;
    for (int kc = 0; kc < Kdim; kc += 16) {
        float4 xv = *(const float4*)(X + (size_t)(m0 + r) * Kdim + kc + c4 * 4);
        float4 wv = *(const float4*)(W + (size_t)(n0 + r) * Kdim + kc + c4 * 4);
        __syncthreads();
        Xs[c4*4+0][r]=xv.x; Xs[c4*4+1][r]=xv.y; Xs[c4*4+2][r]=xv.z; Xs[c4*4+3][r]=xv.w;
        Ws[c4*4+0][r]=wv.x; Ws[c4*4+1][r]=wv.y; Ws[c4*4+2][r]=wv.z; Ws[c4*4+3][r]=wv.w;
        __syncthreads();
#pragma unroll
        for (int cc = 0; cc < 16; cc++) {
            float4 a = *(const float4*)&Xs[cc][ty*4];
            float4 bv = *(const float4*)&Ws[cc][tx*4];
            acc[0][0]+=a.x*bv.x; acc[0][1]+=a.x*bv.y; acc[0][2]+=a.x*bv.z; acc[0][3]+=a.x*bv.w;
            acc[1][0]+=a.y*bv.x; acc[1][1]+=a.y*bv.y; acc[1][2]+=a.y*bv.z; acc[1][3]+=a.y*bv.w;
            acc[2][0]+=a.z*bv.x; acc[2][1]+=a.z*bv.y; acc[2][2]+=a.z*bv.z; acc[2][3]+=a.z*bv.w;
            acc[3][0]+=a.w*bv.x; acc[3][1]+=a.w*bv.y; acc[3][2]+=a.w*bv.z; acc[3][3]+=a.w*bv.w;
        }
    }
#pragma unroll
    for (int rr = 0; rr < 4; rr++)
#pragma unroll
        for (int cc = 0; cc < 4; cc++)
            Y[(size_t)(m0+ty*4+rr) * Ndim + n0+tx*4+cc] = (acc[rr][cc] + bias[n0+tx*4+cc]) * scale;
}

__global__ __launch_bounds__(256)
void softmax_kernel(const int* __restrict__ adj, float* __restrict__ out_attn)
{
    int i = blockIdx.x, h = blockIdx.y, b = blockIdx.z;
    int tid = threadIdx.x;
    __shared__ float red1[8];
    __shared__ float red2[8];
    size_t lbase = (((size_t)b * Hh + h) * Ll + i) * Ll;
    float x = g_logits[lbase + tid];
    bool masked = (adj[((size_t)b * Ll + i) * Ll + tid] == 1);
    float xv = masked ? -CUDART_INF_F : x;
    float mx = xv;
#pragma unroll
    for (int o = 16; o > 0; o >>= 1) mx = fmaxf(mx, __shfl_xor_sync(0xffffffffu, mx, o));
    if ((tid & 31) == 0) red1[tid >> 5] = mx;
    __syncthreads();
    mx = red1[0];
#pragma unroll
    for (int ww = 1; ww < 8; ww++) mx = fmaxf(mx, red1[ww]);
    float e = masked ? 0.f : expf(xv - mx);
    float s = e;
#pragma unroll
    for (int o = 16; o > 0; o >>= 1) s += __shfl_xor_sync(0xffffffffu, s, o);
    if ((tid & 31) == 0) red2[tid >> 5] = s;
    __syncthreads();
    s = red2[0];
#pragma unroll
    for (int ww = 1; ww < 8; ww++) s += red2[ww];
    float wgt = e / s;
    g_w[lbase + tid] = wgt;
    out_attn[(((size_t)b * Ll + i) * Ll + tid) * Hh + h] = wgt;
}

#define PV_SMEM_BYTES ((64*256 + 256*64) * 4)
__global__ __launch_bounds__(256, 1)
void pv_kernel()
{
    extern __shared__ float sm[];
    float* Ws = sm;
    float* Vs = sm + 64 * 256;
    int it = blockIdx.x, h = blockIdx.y, b = blockIdx.z;
    int i0 = it * 64;
    int tid = threadIdx.x;
    size_t wbase = (((size_t)b * Hh + h) * Ll + i0) * Ll;
    const float4* wsrc = (const float4*)(g_w + wbase);
    float4* wdst = (float4*)Ws;
    for (int idx = tid; idx < 64 * 256 / 4; idx += 256) wdst[idx] = wsrc[idx];
    float4* vdst = (float4*)Vs;
    for (int idx = tid; idx < 256 * 64 / 4; idx += 256) {
        int jrow = idx >> 4, d4 = idx & 15;
        vdst[idx] = *(const float4*)(g_v + ((size_t)b * Ll + jrow) * Ee + h * 64 + d4 * 4);
    }
    __syncthreads();
    int i = tid >> 2, t = tid & 3;
    float acc[16];
#pragma unroll
    for (int dd = 0; dd < 16; dd++) acc[dd] = 0.f;
    const float* wrow = Ws + i * 256;
    for (int jj = 0; jj < 256; jj += 4) {
        float4 wv = *(const float4*)(wrow + jj);
#pragma unroll
        for (int u = 0; u < 4; u++) {
            float wsc = (u == 0) ? wv.x : (u == 1) ? wv.y : (u == 2) ? wv.z : wv.w;
            const float* vr = Vs + (jj + u) * 64 + t * 16;
#pragma unroll
            for (int dd = 0; dd < 16; dd++) acc[dd] += wsc * vr[dd];
        }
    }
    float* op = g_o1 + ((size_t)b * Ll + i0 + i) * Ee + h * 64 + t * 16;
#pragma unroll
    for (int dd = 0; dd < 16; dd++) op[dd] = acc[dd];
}

// ---------------------------------------------------------------------------
extern "C" void kernel_launch(void* const* d_in, const int* in_sizes, int n_in,
                              void* d_out, int out_size)
{
    (void)in_sizes; (void)n_in; (void)out_size;
    const float* queries  = (const float*)d_in[0];
    const float* keys     = (const float*)d_in[1];
    const float* values   = (const float*)d_in[2];
    const float* relation = (const float*)d_in[3];
    const int*   adj      = (const int*)d_in[4];
    const float* Wq = (const float*)d_in[5];
    const float* bq = (const float*)d_in[6];
    const float* Wk = (const float*)d_in[7];
    const float* bk = (const float*)d_in[8];
    const float* Wv = (const float*)d_in[9];
    const float* bv = (const float*)d_in[10];
    const float* Wr = (const float*)d_in[11];
    const float* Wo = (const float*)d_in[12];
    const float* bo = (const float*)d_in[13];

    float* out      = (float*)d_out;
    float* out_attn = out + Bb * Ll * Ee;

    float *qp, *kp, *vp, *o1p;
    cudaGetSymbolAddress((void**)&qp,  g_q);
    cudaGetSymbolAddress((void**)&kp,  g_k);
    cudaGetSymbolAddress((void**)&vp,  g_v);
    cudaGetSymbolAddress((void**)&o1p, g_o1);

    cudaFuncSetAttribute(rel_attn_mma_kernel, cudaFuncAttributeMaxDynamicSharedMemorySize, MMA_SMEM);
    cudaFuncSetAttribute(pv_kernel, cudaFuncAttributeMaxDynamicSharedMemorySize, PV_SMEM_BYTES);

    split_rel_kernel<<<(Bb*Ll*Ll*Ee/4)/256, 256>>>((const float4*)relation);
    split_w_kernel<<<1024, 128>>>(Wr);

    dim3 gproj(Ee / 64, (Bb * Ll) / 64);
    gemm_bias_kernel<<<gproj, 256>>>(queries, Wq, bq, qp, Bb*Ll, Ee, Ee, QSCALE);
    gemm_bias_kernel<<<gproj, 256>>>(keys,    Wk, bk, kp, Bb*Ll, Ee, Ee, 1.0f);
    gemm_bias_kernel<<<gproj, 256>>>(values,  Wv, bv, vp, Bb*Ll, Ee, Ee, 1.0f);

    rel_attn_mma_kernel<<<dim3(2, Ll, Bb), 256, MMA_SMEM>>>();

    softmax_kernel<<<dim3(Ll, Hh, Bb), 256>>>(adj, out_attn);

    pv_kernel<<<dim3(Ll / 64, Hh, Bb), 256, PV_SMEM_BYTES>>>();

    gemm_bias_kernel<<<gproj, 256>>>(o1p, Wo, bo, out, Bb*Ll, Ee, Ee, 1.0f);
}

// round 6
// speedup vs baseline: 6.2352x; 1.8037x over previous
#include <cuda_runtime.h>
#include <cuda_bf16.h>
#include <cstdint>
#include <math_constants.h>

#define Bb 2
#define Ll 256
#define Ee 512
#define Hh 8
#define QSCALE 0.125f

// ---------------- device scratch ----------------
__device__ float g_q[Bb*Ll*Ee];
__device__ float g_k[Bb*Ll*Ee];
__device__ float g_v[Bb*Ll*Ee];
__device__ float g_logits[(size_t)Bb*Hh*Ll*Ll];
__device__ float g_w[(size_t)Bb*Hh*Ll*Ll];
__device__ float g_o1[Bb*Ll*Ee];
__device__ __nv_bfloat16 g_rel_hi[(size_t)Bb*Ll*Ll*Ee];
__device__ __nv_bfloat16 g_rel_lo[(size_t)Bb*Ll*Ll*Ee];
__device__ __nv_bfloat16 g_w_hi[1024*512];  // [h*128+p][k]; p<64: Wrq rows, p>=64: Wrk rows
__device__ __nv_bfloat16 g_w_lo[1024*512];
__device__ int g_cnt[Bb];
__device__ unsigned short g_list[Bb*Ll*Ll];   // packed (j<<8)|i of unmasked pairs

// ==================== PTX helpers (sm_103 baseline only) ====================
__device__ __forceinline__ uint32_t smem_u32(const void* p) {
    uint32_t a;
    asm("{ .reg .u64 t; cvta.to.shared.u64 t, %1; cvt.u32.u64 %0, t; }" : "=r"(a) : "l"(p));
    return a;
}
#define SMEM_SWZ(o) ((o) ^ (((o) >> 3) & 0x70))
#define CP_ASYNC16(dst, src) \
    asm volatile("cp.async.cg.shared.global [%0], [%1], 16;" :: "r"(dst), "l"(src))
#define CP_COMMIT() asm volatile("cp.async.commit_group;" ::: "memory")
#define CP_WAIT1() asm volatile("cp.async.wait_group 1;" ::: "memory")
#define CP_WAIT0() asm volatile("cp.async.wait_group 0;" ::: "memory")

__device__ __forceinline__ void ldmx4(uint32_t& r0, uint32_t& r1, uint32_t& r2, uint32_t& r3, uint32_t addr) {
    asm volatile("ldmatrix.sync.aligned.m8n8.x4.shared.b16 {%0,%1,%2,%3}, [%4];"
        : "=r"(r0), "=r"(r1), "=r"(r2), "=r"(r3) : "r"(addr));
}
__device__ __forceinline__ void mma_bf16(float* c, const uint32_t* a, uint32_t b0, uint32_t b1) {
    asm volatile("mma.sync.aligned.m16n8k16.row.col.f32.bf16.bf16.f32 "
        "{%0,%1,%2,%3}, {%4,%5,%6,%7}, {%8,%9}, {%0,%1,%2,%3};"
        : "+f"(c[0]), "+f"(c[1]), "+f"(c[2]), "+f"(c[3])
        : "r"(a[0]), "r"(a[1]), "r"(a[2]), "r"(a[3]), "r"(b0), "r"(b1));
}

// ==================== split kernels ====================
__device__ __forceinline__ void split4(float4 v, __nv_bfloat16* hp, __nv_bfloat16* lp) {
    __nv_bfloat16 h0=__float2bfloat16_rn(v.x), h1=__float2bfloat16_rn(v.y);
    __nv_bfloat16 h2=__float2bfloat16_rn(v.z), h3=__float2bfloat16_rn(v.w);
    ((__nv_bfloat162*)hp)[0] = __nv_bfloat162{h0,h1};
    ((__nv_bfloat162*)hp)[1] = __nv_bfloat162{h2,h3};
    ((__nv_bfloat162*)lp)[0] = __nv_bfloat162{__float2bfloat16_rn(v.x-__bfloat162float(h0)),
                                              __float2bfloat16_rn(v.y-__bfloat162float(h1))};
    ((__nv_bfloat162*)lp)[1] = __nv_bfloat162{__float2bfloat16_rn(v.z-__bfloat162float(h2)),
                                              __float2bfloat16_rn(v.w-__bfloat162float(h3))};
}
__global__ void split_rel_kernel(const float4* __restrict__ x) {
    size_t i = (size_t)blockIdx.x * 256 + threadIdx.x;
    split4(x[i], g_rel_hi + i*4, g_rel_lo + i*4);
}
__global__ void split_w_kernel(const float* __restrict__ Wr) {
    int r = blockIdx.x;                 // 0..1023
    int h = r >> 7, p = r & 127;
    int in_row = (p < 64) ? (h*64 + p) : (512 + h*64 + (p - 64));
    int t = threadIdx.x;                // 128 threads
    float4 v = ((const float4*)(Wr + (size_t)in_row * 512))[t];
    split4(v, g_w_hi + (size_t)r*512 + t*4, g_w_lo + (size_t)r*512 + t*4);
}

// ==================== mask compaction ====================
__global__ void zero_cnt_kernel() {
    if (threadIdx.x < Bb) g_cnt[threadIdx.x] = 0;
}
// Block per (j, b); thread = i. Appends (j<<8)|i for unmasked pairs.
__global__ __launch_bounds__(256)
void compact_kernel(const int* __restrict__ adj) {
    int j = blockIdx.x, b = blockIdx.y, i = threadIdx.x;
    int lane = i & 31, w = i >> 5;
    bool keep = adj[((size_t)(b * Ll + i)) * Ll + j] != 1;
    unsigned m = __ballot_sync(0xffffffffu, keep);
    int wpos = __popc(m & ((1u << lane) - 1));
    __shared__ int wcnt[8], wbase[9];
    if (lane == 0) wcnt[w] = __popc(m);
    __syncthreads();
    if (i == 0) {
        int s = 0;
        for (int x = 0; x < 8; x++) { wbase[x] = s; s += wcnt[x]; }
        wbase[8] = atomicAdd(&g_cnt[b], s);
    }
    __syncthreads();
    if (keep) g_list[b * (Ll*Ll) + wbase[8] + wbase[w] + wpos] = (unsigned short)((j << 8) | i);
}

// ==================== mma.sync relation attention (compacted rows) ====================
// CTA = tile t of 128 unmasked (j,i) pairs for batch b. Heads looped inside;
// per head 24 K-chunks of 64: splits [Ah*Bh | Ah*Bl | Al*Bh]. 3-stage cp.async.
// Warps: 4m x 2n; warp tile 32(M) x 64(N, matched rq/rk halves).
#define NSTG 3
#define STG_BYTES 32768         // A 16KB + B 16KB
#define MMA_SMEM (NSTG*STG_BYTES + 1024 + 256)

__global__ void __launch_bounds__(256, 2) rel_attn_mma_kernel()
{
    extern __shared__ char smem[];
    float* parr = (float*)(smem + NSTG * STG_BYTES);
    unsigned short* sidx = (unsigned short*)(smem + NSTG * STG_BYTES + 1024);
    const uint32_t sb = smem_u32(smem);
    const int tid = threadIdx.x, lane = tid & 31, w = tid >> 5;
    const int wm = w & 3, wn = w >> 2;
    const int t = blockIdx.x, b = blockIdx.y;

    const int cnt = g_cnt[b];
    if (t * 128 >= cnt) return;

    if (tid < 128) sidx[tid] = g_list[b * (Ll*Ll) + t * 128 + tid];
    __syncthreads();

    float c[2][8][4];
#pragma unroll
    for (int mt = 0; mt < 2; mt++)
#pragma unroll
        for (int g = 0; g < 8; g++)
#pragma unroll
            for (int e = 0; e < 4; e++) c[mt][g][e] = 0.f;

    auto issue = [&](int gc) {
        const int h = gc / 24, cc = gc % 24;
        const int split = cc >> 3;
        const int kc = (cc & 7) * 64;
        const __nv_bfloat16* Aarr = (split == 2) ? g_rel_lo : g_rel_hi;
        const __nv_bfloat16* Bptr = ((split == 1) ? g_w_lo : g_w_hi) + (size_t)h * 128 * 512;
        const uint32_t stA = sb + (gc % NSTG) * STG_BYTES;
        const uint32_t stB = stA + 16384;
#pragma unroll
        for (int r4 = 0; r4 < 4; r4++) {
            int idx = tid + r4 * 256;       // 1024 16B units each
            int row = idx >> 3, u = idx & 7;
            int e = sidx[row];              // gathered (j,i) -> rel row b*65536+e
            CP_ASYNC16(stA + SMEM_SWZ(row * 128 + u * 16),
                       Aarr + ((size_t)(b * (Ll*Ll)) + e) * 512 + kc + u * 8);
            CP_ASYNC16(stB + SMEM_SWZ(row * 128 + u * 16),
                       Bptr + (size_t)row * 512 + kc + u * 8);
        }
        CP_COMMIT();
    };

    issue(0); issue(1);

    for (int gc = 0; gc < 192; gc++) {
        if (gc + 2 < 192) { CP_WAIT1(); } else { CP_WAIT0(); }
        __syncthreads();
        if (gc + 2 < 192) issue(gc + 2);

        const uint32_t stA = sb + (gc % NSTG) * STG_BYTES;
        const uint32_t stB = stA + 16384;
        const int r8 = lane & 7, sel = lane >> 3;
#pragma unroll
        for (int ks = 0; ks < 4; ks++) {
            const int k0 = ks * 16;
            uint32_t a[2][4];
#pragma unroll
            for (int mt = 0; mt < 2; mt++) {
                int row = wm * 32 + mt * 16 + r8 + (sel & 1) * 8;
                int c16 = (k0 >> 3) + (sel >> 1);
                ldmx4(a[mt][0], a[mt][1], a[mt][2], a[mt][3], stA + SMEM_SWZ(row * 128 + c16 * 16));
            }
            uint32_t bq[4][2], bk[4][2];
#pragma unroll
            for (int gp = 0; gp < 2; gp++) {
                int c16 = (k0 >> 3) + (sel & 1);
                {
                    int row = wn * 32 + gp * 16 + r8 + (sel >> 1) * 8;
                    ldmx4(bq[gp*2][0], bq[gp*2][1], bq[gp*2+1][0], bq[gp*2+1][1],
                          stB + SMEM_SWZ(row * 128 + c16 * 16));
                }
                {
                    int row = 64 + wn * 32 + gp * 16 + r8 + (sel >> 1) * 8;
                    ldmx4(bk[gp*2][0], bk[gp*2][1], bk[gp*2+1][0], bk[gp*2+1][1],
                          stB + SMEM_SWZ(row * 128 + c16 * 16));
                }
            }
#pragma unroll
            for (int mt = 0; mt < 2; mt++)
#pragma unroll
                for (int g = 0; g < 4; g++) {
                    mma_bf16(c[mt][g],   a[mt], bq[g][0], bq[g][1]);
                    mma_bf16(c[mt][4+g], a[mt], bk[g][0], bk[g][1]);
                }
        }

        if ((gc % 24) == 23) {
            // -------- epilogue for head h --------
            const int h = gc / 24;
#pragma unroll
            for (int mt = 0; mt < 2; mt++)
#pragma unroll
                for (int rh = 0; rh < 2; rh++) {
                    const int R = wm * 32 + mt * 16 + (lane >> 2) + rh * 8;
                    const int e = sidx[R];
                    const float* qrow = g_q + ((size_t)(b * Ll + (e & 255))) * Ee + h * 64;
                    const float* krow = g_k + ((size_t)(b * Ll + (e >> 8))) * Ee + h * 64;
                    float acc = 0.f;
#pragma unroll
                    for (int g = 0; g < 4; g++) {
                        const int d0 = wn * 32 + g * 8 + 2 * (lane & 3);
                        acc += (qrow[d0]     + c[mt][g][rh*2+0]) * (krow[d0]     + c[mt][4+g][rh*2+0]);
                        acc += (qrow[d0 + 1] + c[mt][g][rh*2+1]) * (krow[d0 + 1] + c[mt][4+g][rh*2+1]);
                    }
                    acc += __shfl_xor_sync(0xffffffffu, acc, 1);
                    acc += __shfl_xor_sync(0xffffffffu, acc, 2);
                    if ((lane & 3) == 0) parr[wn * 128 + R] = acc;
                }
            __syncthreads();
            if (tid < 128 && t * 128 + tid < cnt) {
                const int e = sidx[tid];
                float lg = parr[tid] + parr[128 + tid];
                g_logits[((size_t)(b * Hh + h) * Ll + (e & 255)) * Ll + (e >> 8)] = lg;
            }
            // reset accumulators for next head
#pragma unroll
            for (int mt = 0; mt < 2; mt++)
#pragma unroll
                for (int g = 0; g < 8; g++)
#pragma unroll
                    for (int e2 = 0; e2 < 4; e2++) c[mt][g][e2] = 0.f;
        }
    }
}

// ==================== small GEMMs ====================
// Batched q/k/v projection: blockIdx.z selects input/weight/output.
__global__ __launch_bounds__(256)
void gemm_qkv_kernel(const float* __restrict__ queries, const float* __restrict__ keys,
                     const float* __restrict__ values,
                     const float* __restrict__ Wq, const float* __restrict__ bq,
                     const float* __restrict__ Wk, const float* __restrict__ bk,
                     const float* __restrict__ Wv, const float* __restrict__ bv)
{
    const int z = blockIdx.z;
    const float* X = (z == 0) ? queries : (z == 1) ? keys : values;
    const float* W = (z == 0) ? Wq : (z == 1) ? Wk : Wv;
    const float* bias = (z == 0) ? bq : (z == 1) ? bk : bv;
    float* Y = (z == 0) ? g_q : (z == 1) ? g_k : g_v;
    const float scale = (z == 0) ? QSCALE : 1.0f;

    __shared__ float Xs[16][64];
    __shared__ float Ws[16][64];
    int tid = threadIdx.x;
    int m0 = blockIdx.y * 64, n0 = blockIdx.x * 64;
    int ty = tid >> 4, tx = tid & 15;
    int r = tid >> 2, c4 = tid & 3;
    float acc[4][4];
#pragma unroll
    for (int a = 0; a < 4; a++)
#pragma unroll
        for (int bb = 0; bb < 4; bb++) acc[a][bb] = 0.f;
    for (int kc = 0; kc < Ee; kc += 16) {
        float4 xv = *(const float4*)(X + (size_t)(m0 + r) * Ee + kc + c4 * 4);
        float4 wv = *(const float4*)(W + (size_t)(n0 + r) * Ee + kc + c4 * 4);
        __syncthreads();
        Xs[c4*4+0][r]=xv.x; Xs[c4*4+1][r]=xv.y; Xs[c4*4+2][r]=xv.z; Xs[c4*4+3][r]=xv.w;
        Ws[c4*4+0][r]=wv.x; Ws[c4*4+1][r]=wv.y; Ws[c4*4+2][r]=wv.z; Ws[c4*4+3][r]=wv.w;
        __syncthreads();
#pragma unroll
        for (int cc = 0; cc < 16; cc++) {
            float4 a = *(const float4*)&Xs[cc][ty*4];
            float4 bv4 = *(const float4*)&Ws[cc][tx*4];
            acc[0][0]+=a.x*bv4.x; acc[0][1]+=a.x*bv4.y; acc[0][2]+=a.x*bv4.z; acc[0][3]+=a.x*bv4.w;
            acc[1][0]+=a.y*bv4.x; acc[1][1]+=a.y*bv4.y; acc[1][2]+=a.y*bv4.z; acc[1][3]+=a.y*bv4.w;
            acc[2][0]+=a.z*bv4.x; acc[2][1]+=a.z*bv4.y; acc[2][2]+=a.z*bv4.z; acc[2][3]+=a.z*bv4.w;
            acc[3][0]+=a.w*bv4.x; acc[3][1]+=a.w*bv4.y; acc[3][2]+=a.w*bv4.z; acc[3][3]+=a.w*bv4.w;
        }
    }
#pragma unroll
    for (int rr = 0; rr < 4; rr++)
#pragma unroll
        for (int cc = 0; cc < 4; cc++)
            Y[(size_t)(m0+ty*4+rr) * Ee + n0+tx*4+cc] = (acc[rr][cc] + bias[n0+tx*4+cc]) * scale;
}

__global__ __launch_bounds__(256)
void gemm_bias_kernel(const float* __restrict__ X, const float* __restrict__ W,
                      const float* __restrict__ bias, float* __restrict__ Y,
                      int Mdim, int Ndim, int Kdim, float scale)
{
    __shared__ float Xs[16][64];
    __shared__ float Ws[16][64];
    int tid = threadIdx.x;
    int m0 = blockIdx.y * 64, n0 = blockIdx.x * 64;
    int ty = tid >> 4, tx = tid & 15;
    int r = tid >> 2, c4 = tid & 3;
    float acc[4][4];
#pragma unroll
    for (int a = 0; a < 4; a++)
#pragma unroll
        for (int bb = 0; bb < 4; bb++) acc[a][bb] = 0.f;
    for (int kc = 0; kc < Kdim; kc += 16) {
        float4 xv = *(const float4*)(X + (size_t)(m0 + r) * Kdim + kc + c4 * 4);
        float4 wv = *(const float4*)(W + (size_t)(n0 + r) * Kdim + kc + c4 * 4);
        __syncthreads();
        Xs[c4*4+0][r]=xv.x; Xs[c4*4+1][r]=xv.y; Xs[c4*4+2][r]=xv.z; Xs[c4*4+3][r]=xv.w;
        Ws[c4*4+0][r]=wv.x; Ws[c4*4+1][r]=wv.y; Ws[c4*4+2][r]=wv.z; Ws[c4*4+3][r]=wv.w;
        __syncthreads();
#pragma unroll
        for (int cc = 0; cc < 16; cc++) {
            float4 a = *(const float4*)&Xs[cc][ty*4];
            float4 bv4 = *(const float4*)&Ws[cc][tx*4];
            acc[0][0]+=a.x*bv4.x; acc[0][1]+=a.x*bv4.y; acc[0][2]+=a.x*bv4.z; acc[0][3]+=a.x*bv4.w;
            acc[1][0]+=a.y*bv4.x; acc[1][1]+=a.y*bv4.y; acc[1][2]+=a.y*bv4.z; acc[1][3]+=a.y*bv4.w;
            acc[2][0]+=a.z*bv4.x; acc[2][1]+=a.z*bv4.y; acc[2][2]+=a.z*bv4.z; acc[2][3]+=a.z*bv4.w;
            acc[3][0]+=a.w*bv4.x; acc[3][1]+=a.w*bv4.y; acc[3][2]+=a.w*bv4.z; acc[3][3]+=a.w*bv4.w;
        }
    }
#pragma unroll
    for (int rr = 0; rr < 4; rr++)
#pragma unroll
        for (int cc = 0; cc < 4; cc++)
            Y[(size_t)(m0+ty*4+rr) * Ndim + n0+tx*4+cc] = (acc[rr][cc] + bias[n0+tx*4+cc]) * scale;
}

// ==================== softmax / PV ====================
__global__ __launch_bounds__(256)
void softmax_kernel(const int* __restrict__ adj, float* __restrict__ out_attn)
{
    int i = blockIdx.x, h = blockIdx.y, b = blockIdx.z;
    int tid = threadIdx.x;
    __shared__ float red1[8];
    __shared__ float red2[8];
    size_t lbase = (((size_t)b * Hh + h) * Ll + i) * Ll;
    float x = g_logits[lbase + tid];
    bool masked = (adj[((size_t)b * Ll + i) * Ll + tid] == 1);
    float xv = masked ? -CUDART_INF_F : x;
    float mx = xv;
#pragma unroll
    for (int o = 16; o > 0; o >>= 1) mx = fmaxf(mx, __shfl_xor_sync(0xffffffffu, mx, o));
    if ((tid & 31) == 0) red1[tid >> 5] = mx;
    __syncthreads();
    mx = red1[0];
#pragma unroll
    for (int ww = 1; ww < 8; ww++) mx = fmaxf(mx, red1[ww]);
    float e = masked ? 0.f : expf(xv - mx);
    float s = e;
#pragma unroll
    for (int o = 16; o > 0; o >>= 1) s += __shfl_xor_sync(0xffffffffu, s, o);
    if ((tid & 31) == 0) red2[tid >> 5] = s;
    __syncthreads();
    s = red2[0];
#pragma unroll
    for (int ww = 1; ww < 8; ww++) s += red2[ww];
    float wgt = e / s;
    g_w[lbase + tid] = wgt;
    out_attn[(((size_t)b * Ll + i) * Ll + tid) * Hh + h] = wgt;
}

#define PV_SMEM_BYTES ((64*256 + 256*64) * 4)
__global__ __launch_bounds__(256, 1)
void pv_kernel()
{
    extern __shared__ float sm[];
    float* Ws = sm;
    float* Vs = sm + 64 * 256;
    int it = blockIdx.x, h = blockIdx.y, b = blockIdx.z;
    int i0 = it * 64;
    int tid = threadIdx.x;
    size_t wbase = (((size_t)b * Hh + h) * Ll + i0) * Ll;
    const float4* wsrc = (const float4*)(g_w + wbase);
    float4* wdst = (float4*)Ws;
    for (int idx = tid; idx < 64 * 256 / 4; idx += 256) wdst[idx] = wsrc[idx];
    float4* vdst = (float4*)Vs;
    for (int idx = tid; idx < 256 * 64 / 4; idx += 256) {
        int jrow = idx >> 4, d4 = idx & 15;
        vdst[idx] = *(const float4*)(g_v + ((size_t)b * Ll + jrow) * Ee + h * 64 + d4 * 4);
    }
    __syncthreads();
    int i = tid >> 2, tq = tid & 3;
    float acc[16];
#pragma unroll
    for (int dd = 0; dd < 16; dd++) acc[dd] = 0.f;
    const float* wrow = Ws + i * 256;
    for (int jj = 0; jj < 256; jj += 4) {
        float4 wv = *(const float4*)(wrow + jj);
#pragma unroll
        for (int u = 0; u < 4; u++) {
            float wsc = (u == 0) ? wv.x : (u == 1) ? wv.y : (u == 2) ? wv.z : wv.w;
            const float* vr = Vs + (jj + u) * 64 + tq * 16;
#pragma unroll
            for (int dd = 0; dd < 16; dd++) acc[dd] += wsc * vr[dd];
        }
    }
    float* op = g_o1 + ((size_t)b * Ll + i0 + i) * Ee + h * 64 + tq * 16;
#pragma unroll
    for (int dd = 0; dd < 16; dd++) op[dd] = acc[dd];
}

// ---------------------------------------------------------------------------
extern "C" void kernel_launch(void* const* d_in, const int* in_sizes, int n_in,
                              void* d_out, int out_size)
{
    (void)in_sizes; (void)n_in; (void)out_size;
    const float* queries  = (const float*)d_in[0];
    const float* keys     = (const float*)d_in[1];
    const float* values   = (const float*)d_in[2];
    const float* relation = (const float*)d_in[3];
    const int*   adj      = (const int*)d_in[4];
    const float* Wq = (const float*)d_in[5];
    const float* bq = (const float*)d_in[6];
    const float* Wk = (const float*)d_in[7];
    const float* bk = (const float*)d_in[8];
    const float* Wv = (const float*)d_in[9];
    const float* bv = (const float*)d_in[10];
    const float* Wr = (const float*)d_in[11];
    const float* Wo = (const float*)d_in[12];
    const float* bo = (const float*)d_in[13];

    float* out      = (float*)d_out;
    float* out_attn = out + Bb * Ll * Ee;

    float *o1p;
    cudaGetSymbolAddress((void**)&o1p, g_o1);

    cudaFuncSetAttribute(rel_attn_mma_kernel, cudaFuncAttributeMaxDynamicSharedMemorySize, MMA_SMEM);
    cudaFuncSetAttribute(pv_kernel, cudaFuncAttributeMaxDynamicSharedMemorySize, PV_SMEM_BYTES);

    zero_cnt_kernel<<<1, 32>>>();
    compact_kernel<<<dim3(Ll, Bb), 256>>>(adj);
    split_rel_kernel<<<(Bb*Ll*Ll*Ee/4)/256, 256>>>((const float4*)relation);
    split_w_kernel<<<1024, 128>>>(Wr);

    gemm_qkv_kernel<<<dim3(Ee/64, (Bb*Ll)/64, 3), 256>>>(queries, keys, values,
                                                         Wq, bq, Wk, bk, Wv, bv);

    rel_attn_mma_kernel<<<dim3(512, Bb), 256, MMA_SMEM>>>();

    softmax_kernel<<<dim3(Ll, Hh, Bb), 256>>>(adj, out_attn);

    pv_kernel<<<dim3(Ll / 64, Hh, Bb), 256, PV_SMEM_BYTES>>>();

    gemm_bias_kernel<<<dim3(Ee/64, (Bb*Ll)/64), 256>>>(o1p, Wo, bo, out, Bb*Ll, Ee, Ee, 1.0f);
}